// round 14
// baseline (speedup 1.0000x reference)
#include <cuda_runtime.h>

#define DDIM 4096
#define NTHREADS 512
#define GRID 148
#define R6 6      // rows per iteration
#define NBUF 2    // cp.async double buffer
#define NROWS 8192

// ---------------------------------------------------------------------------
// Compact-WY form of 8 sequential Householder reflections:
//   x_out = x - U d,  d = S c,  c = U^T x,  S = 2*(I+2L)^{-1}, U normalized.
//
// Persistent kernel, 1 CTA/SM, R10 schedule with 6 rows/iteration:
//   u fully register-resident (64 regs/thread, zero u smem traffic);
//   x streams through a double-buffered cp.async ring (per-thread private
//   slots) and is read from smem in both the dot and update phases;
//   rows 0-3 reduced by the 31-shfl val[32] butterfly, rows 4-5 by a
//   16-value butterfly; warp0/warp1 finish the two groups in parallel
//   between the same barrier pair. 2 barriers per 6 rows.
// smem: xbuf[2][6*4096] | wsum[16*32] | wsum2[16*16] | dsh2[96] | Ssh[64]
//       | gsh[36] | rn[8]   (~195.9 KB)
// ---------------------------------------------------------------------------
extern __shared__ float smem[];

typedef unsigned long long u64;

__device__ __forceinline__ u64 ffma2(u64 a, u64 b, u64 c) {
    u64 d;
    asm("fma.rn.f32x2 %0, %1, %2, %3;" : "=l"(d) : "l"(a), "l"(b), "l"(c));
    return d;
}
__device__ __forceinline__ u64 pack2(float lo, float hi) {
    u64 d;
    asm("mov.b64 %0, {%1, %2};" : "=l"(d) : "f"(lo), "f"(hi));
    return d;
}
__device__ __forceinline__ void unpack2(u64 p, float& lo, float& hi) {
    asm("mov.b64 {%0, %1}, %2;" : "=f"(lo), "=f"(hi) : "l"(p));
}
__device__ __forceinline__ int tri_idx(int a, int b) {
    return a * (17 - a) / 2 + (b - a);  // packed upper-tri [36], a <= b
}

__global__ void __launch_bounds__(NTHREADS, 1)
hra_kernel(const float* __restrict__ X, const float* __restrict__ hra_u,
           float* __restrict__ Y, int nq) {
    float* xbuf  = smem;                          // 2 * 6*4096
    float* wsum  = xbuf + NBUF * R6 * DDIM;       // 16*32
    float* wsum2 = wsum + 16 * 32;                // 16*16
    float* dsh2f = wsum2 + 16 * 16;               // 96 floats = 48 u64
    float* Ssh   = dsh2f + 96;                    // 64
    float* gsh   = Ssh + 64;                      // 36
    float* rn    = gsh + 36;                      // 8

    const int tid  = threadIdx.x;
    const int lane = tid & 31;
    const int warp = tid >> 5;

    // ---------------- Phase 0: Gram + S + per-thread u registers ----------
    if (tid < 36) gsh[tid] = 0.f;
    __syncthreads();
    {
        float acc[36];
#pragma unroll
        for (int t = 0; t < 36; t++) acc[t] = 0.f;
        for (int k = tid; k < DDIM; k += NTHREADS) {
            float4 a = reinterpret_cast<const float4*>(hra_u)[k * 2];
            float4 b = reinterpret_cast<const float4*>(hra_u)[k * 2 + 1];
            float v[8] = {a.x, a.y, a.z, a.w, b.x, b.y, b.z, b.w};
            int t = 0;
#pragma unroll
            for (int i = 0; i < 8; i++)
#pragma unroll
                for (int j = i; j < 8; j++)
                    acc[t++] += v[i] * v[j];
        }
#pragma unroll
        for (int t = 0; t < 36; t++) {
#pragma unroll
            for (int o = 16; o > 0; o >>= 1)
                acc[t] += __shfl_xor_sync(0xffffffffu, acc[t], o);
        }
        if (lane == 0)
            for (int t = 0; t < 36; t++) atomicAdd(&gsh[t], acc[t]);
    }
    __syncthreads();
    if (tid < 8) rn[tid] = rsqrtf(gsh[tri_idx(tid, tid)]);
    __syncthreads();
    if (tid < 8) {
        const int c = tid;  // column c of S: solve (I + 2L) x = 2 e_c
        float x[8];
#pragma unroll
        for (int i = 0; i < 8; i++) {
            float s = (i == c) ? 2.f : 0.f;
            for (int j = 0; j < i; j++) {
                float gji = gsh[tri_idx(j, i)] * rn[j] * rn[i];
                s -= 2.f * gji * x[j];
            }
            x[i] = s;
            Ssh[i * 8 + c] = x[i];
        }
    }
    __syncthreads();  // rn, Ssh ready

    // per-thread u registers: elements [4*tid, 4*tid+4) (chunk 0) and
    // [2048+4*tid, 2048+4*tid+4) (chunk 1) of each normalized vector.
    u64 up[8][4];
    {
        const float4* hu4 = reinterpret_cast<const float4*>(hra_u);
#pragma unroll
        for (int c = 0; c < 2; c++) {
            float uu[4][8];
#pragma unroll
            for (int e = 0; e < 4; e++) {
                int k = c * 2048 + 4 * tid + e;
                float4 t0 = hu4[k * 2 + 0];
                float4 t1 = hu4[k * 2 + 1];
                uu[e][0] = t0.x; uu[e][1] = t0.y; uu[e][2] = t0.z; uu[e][3] = t0.w;
                uu[e][4] = t1.x; uu[e][5] = t1.y; uu[e][6] = t1.z; uu[e][7] = t1.w;
            }
#pragma unroll
            for (int i = 0; i < 8; i++) {
                float r = rn[i];
                up[i][c * 2 + 0] = pack2(uu[0][i] * r, uu[1][i] * r);
                up[i][c * 2 + 1] = pack2(uu[2][i] * r, uu[3][i] * r);
            }
        }
    }

    // ---------------- Phase 1: main loop (6 rows / iteration) --------------
    const int t_self = (int)(__brev((unsigned)lane) >> 27);  // bitrev5(lane)
    const int t16 = ((lane & 1) << 3) | ((lane & 2) << 1) |
                    ((lane & 4) >> 1) | ((lane & 8) >> 3);   // bitrev4(lane&15)
    const unsigned xb_base = (unsigned)__cvta_generic_to_shared(xbuf);
    const unsigned BUF_BYTES = R6 * DDIM * 4u;

    // prefetch rows [q*6, q*6+6) (clamped) into buffer `buf`
#define PREFETCH6(buf, qq)                                                    \
    do {                                                                      \
        _Pragma("unroll")                                                     \
        for (int r = 0; r < R6; r++) {                                        \
            int rowg = (qq) * R6 + r;                                         \
            if (rowg > NROWS - 1) rowg = NROWS - 1;                           \
            const float4* xg = reinterpret_cast<const float4*>(X)             \
                             + (size_t)rowg * 1024;                           \
            _Pragma("unroll")                                                 \
            for (int h = 0; h < 2; h++) {                                     \
                unsigned s = xb_base + (buf) * BUF_BYTES                      \
                           + (unsigned)(r * 1024 + h * NTHREADS + tid) * 16u; \
                const float4* g = xg + (h * NTHREADS + tid);                  \
                asm volatile("cp.async.cg.shared.global [%0], [%1], 16;"      \
                             :: "r"(s), "l"(g));                              \
            }                                                                 \
        }                                                                     \
        asm volatile("cp.async.commit_group;");                               \
    } while (0)

    int q = blockIdx.x;
    if (q >= nq) return;

    PREFETCH6(0, q);

    int bcur = 0;
    for (; q < nq; q += GRID) {
        asm volatile("cp.async.wait_group 0;");

        const ulonglong2* xb2 =
            reinterpret_cast<const ulonglong2*>(xbuf + bcur * (R6 * DDIM));

        // ---- dots rows 0-3 -> val[32] ----
        float val[32];
#pragma unroll
        for (int r = 0; r < 4; r++) {
            ulonglong2 xa = xb2[r * 1024 + tid];
            ulonglong2 xc = xb2[r * 1024 + tid + NTHREADS];
#pragma unroll
            for (int i = 0; i < 8; i++) {
                u64 a0 = ffma2(xa.x, up[i][0], 0ull);
                u64 a1 = ffma2(xa.y, up[i][1], 0ull);
                a0 = ffma2(xc.x, up[i][2], a0);
                a1 = ffma2(xc.y, up[i][3], a1);
                float l0, h0, l1, h1;
                unpack2(a0, l0, h0);
                unpack2(a1, l1, h1);
                val[r * 8 + i] = (l0 + h0) + (l1 + h1);
            }
        }
        // 31-shfl butterfly; lane ends with sum of val[bitrev5(lane)]
#pragma unroll
        for (int s = 0; s < 5; s++) {
            const int m = 1 << s;
            const int h = 16 >> s;
#pragma unroll
            for (int k = 0; k < h; k++) {
                float send = (lane & m) ? val[k] : val[k + h];
                float rec  = __shfl_xor_sync(0xffffffffu, send, m);
                float keep = (lane & m) ? val[k + h] : val[k];
                val[k] = keep + rec;
            }
        }
        wsum[warp * 32 + t_self] = val[0];

        // ---- dots rows 4-5 -> val2[16] ----
        float val2[16];
#pragma unroll
        for (int r2 = 0; r2 < 2; r2++) {
            const int r = 4 + r2;
            ulonglong2 xa = xb2[r * 1024 + tid];
            ulonglong2 xc = xb2[r * 1024 + tid + NTHREADS];
#pragma unroll
            for (int i = 0; i < 8; i++) {
                u64 a0 = ffma2(xa.x, up[i][0], 0ull);
                u64 a1 = ffma2(xa.y, up[i][1], 0ull);
                a0 = ffma2(xc.x, up[i][2], a0);
                a1 = ffma2(xc.y, up[i][3], a1);
                float l0, h0, l1, h1;
                unpack2(a0, l0, h0);
                unpack2(a1, l1, h1);
                val2[r2 * 8 + i] = (l0 + h0) + (l1 + h1);
            }
        }
        // 16-value butterfly (4 stages) + halves fold
#pragma unroll
        for (int s = 0; s < 4; s++) {
            const int m = 1 << s;
            const int h = 8 >> s;
#pragma unroll
            for (int k = 0; k < h; k++) {
                float send = (lane & m) ? val2[k] : val2[k + h];
                float rec  = __shfl_xor_sync(0xffffffffu, send, m);
                float keep = (lane & m) ? val2[k + h] : val2[k];
                val2[k] = keep + rec;
            }
        }
        val2[0] += __shfl_xor_sync(0xffffffffu, val2[0], 16);
        if (lane < 16) wsum2[warp * 16 + t16] = val2[0];

        // prefetch next iteration's rows into the other buffer
        // (after all dot-phase LDS; update-phase LDS of that buffer happened
        //  a full dots-phase ago -> WAR-safe for private slots)
        {
            int qn = q + GRID;
            int qc = qn < nq ? qn : q;
            PREFETCH6(bcur ^ 1, qc);
        }
        __syncthreads();  // bar1: wsum + wsum2 ready

        // warp0 finishes rows 0-3; warp1 finishes rows 4-5 (parallel)
        if (warp == 0) {
            float c = 0.f;
#pragma unroll
            for (int w = 0; w < 16; w++) c += wsum[w * 32 + lane];
            const int i = lane & 7;
            float d = 0.f;
#pragma unroll
            for (int j = 0; j < 8; j++) {
                float cj = __shfl_sync(0xffffffffu, c, (lane & 24) + j);
                d += Ssh[i * 8 + j] * cj;
            }
            reinterpret_cast<u64*>(dsh2f)[lane] = pack2(-d, -d);  // rows 0-3
        } else if (warp == 1) {
            float c = 0.f;
            const int l16 = lane & 15;
#pragma unroll
            for (int w = 0; w < 16; w++) c += wsum2[w * 16 + l16];
            const int i = lane & 7;
            float d = 0.f;
#pragma unroll
            for (int j = 0; j < 8; j++) {
                float cj = __shfl_sync(0xffffffffu, c, (lane & 24) + j);
                d += Ssh[i * 8 + j] * cj;
            }
            if (lane < 16)
                reinterpret_cast<u64*>(dsh2f)[32 + lane] = pack2(-d, -d);  // rows 4-5
        }
        __syncthreads();  // bar2: dsh2f ready

        // ---- rank-8 update + guarded streaming store (x re-read) ----
        {
            const ulonglong2* dq = reinterpret_cast<const ulonglong2*>(dsh2f);
            const int rowbase = q * R6;
#pragma unroll
            for (int r = 0; r < R6; r++) {
                if (rowbase + r >= NROWS) break;
                ulonglong2 p0 = dq[r * 4 + 0];
                ulonglong2 p1 = dq[r * 4 + 1];
                ulonglong2 p2 = dq[r * 4 + 2];
                ulonglong2 p3 = dq[r * 4 + 3];
                u64 nd[8] = {p0.x, p0.y, p1.x, p1.y, p2.x, p2.y, p3.x, p3.y};

                ulonglong2 xa = xb2[r * 1024 + tid];
                ulonglong2 xc = xb2[r * 1024 + tid + NTHREADS];
                u64 w0 = xa.x, w1 = xa.y, w2 = xc.x, w3 = xc.y;
#pragma unroll
                for (int i = 0; i < 8; i++) {
                    w0 = ffma2(nd[i], up[i][0], w0);
                    w1 = ffma2(nd[i], up[i][1], w1);
                    w2 = ffma2(nd[i], up[i][2], w2);
                    w3 = ffma2(nd[i], up[i][3], w3);
                }
                float4 o0, o1;
                unpack2(w0, o0.x, o0.y); unpack2(w1, o0.z, o0.w);
                unpack2(w2, o1.x, o1.y); unpack2(w3, o1.z, o1.w);
                float4* y4 = reinterpret_cast<float4*>(Y)
                           + (size_t)(rowbase + r) * 1024;
                __stcs(&y4[tid], o0);
                __stcs(&y4[tid + NTHREADS], o1);
            }
        }

        bcur ^= 1;
    }
#undef PREFETCH6
}

extern "C" void kernel_launch(void* const* d_in, const int* in_sizes, int n_in,
                              void* d_out, int out_size) {
    const float* X = (const float*)d_in[0];      // (4, 2048, 4096) fp32
    const float* hra_u = (const float*)d_in[1];  // (4096, 8) fp32
    float* Y = (float*)d_out;

    const int nq = (NROWS + R6 - 1) / R6;        // 1366

    const size_t smem_bytes =
        (NBUF * R6 * DDIM + 16 * 32 + 16 * 16 + 96 + 64 + 36 + 8) * sizeof(float);
    cudaFuncSetAttribute(hra_kernel,
                         cudaFuncAttributeMaxDynamicSharedMemorySize,
                         (int)smem_bytes);

    hra_kernel<<<GRID, NTHREADS, smem_bytes>>>(X, hra_u, Y, nq);
}